// round 10
// baseline (speedup 1.0000x reference)
#include <cuda_runtime.h>

#define BB 4
#define SS 2048
#define HH 16
#define NPAIR 64
#define NB (NPAIR*16)          // 1024 blocks: (pair, tile)
#define L2E 1.44269504088896340736f

__device__ __forceinline__ float ex2f(float x) {
    float r; asm("ex2.approx.ftz.f32 %0, %1;" : "=f"(r) : "f"(x)); return r;
}

// ---------------------------------------------------------------------------
// Single fused kernel: qkv recompute + causal attention + rank-1 projection
// scatter. Block = (pair=(b,h), tile); 128 threads, one query each.
// Heavy tiles launch first (low blockIdx) for wave balance.
// out must be zeroed before launch (memsetAsync); each head atomically adds
// o_h * wo[h,:] + bo/16 into its 16 output columns.
// ---------------------------------------------------------------------------
__global__ void __launch_bounds__(128) attn_kernel(
    const float* __restrict__ x,   // [8192, 16]
    const float* __restrict__ wq,  // [16, 48]
    const float* __restrict__ bq,  // [48]
    const float* __restrict__ wo,  // [16, 16]
    const float* __restrict__ bo,  // [16]
    float* __restrict__ out)       // [8192, 16], pre-zeroed
{
    __shared__ float2 skv[SS];        // 16 KB (only [0, tile_end) used)
    __shared__ float  swq[16];        // q-weights * log2(e)
    __shared__ float  swk[16], swv[16];
    __shared__ float  swo[16];        // wo[h, :]
    __shared__ float  sbias[3];       // bq_q*L2E, bq_k, bq_v
    __shared__ float  sbo[16];        // bo / 16

    int t    = threadIdx.x;
    int bx   = blockIdx.x;
    int pair = bx & (NPAIR - 1);
    int tile = 15 - (bx >> 6);        // heavy-first
    int tile_end = (tile + 1) << 7;
    int b = pair >> 4, h = pair & 15;

    // Stage this head's weight columns into smem.
    if (t < 16) {
        swq[t] = wq[t * 48 + h] * L2E;
        swk[t] = wq[t * 48 + h + 16];
        swv[t] = wq[t * 48 + h + 32];
        swo[t] = wo[h * 16 + t];
        sbo[t] = bo[t] * 0.0625f;
    }
    if (t == 0) {
        sbias[0] = bq[h] * L2E;
        sbias[1] = bq[h + 16];
        sbias[2] = bq[h + 32];
    }
    __syncthreads();

    const float* xb = x + b * SS * 16;

    // Stage k,v for positions [0, tile_end) (recomputed from x).
    for (int j = t; j < tile_end; j += 128) {
        const float4* xr = reinterpret_cast<const float4*>(xb + j * 16);
        float4 x0 = xr[0], x1 = xr[1], x2 = xr[2], x3 = xr[3];
        float xv[16] = { x0.x, x0.y, x0.z, x0.w, x1.x, x1.y, x1.z, x1.w,
                         x2.x, x2.y, x2.z, x2.w, x3.x, x3.y, x3.z, x3.w };
        float ak = sbias[1], av = sbias[2];
        #pragma unroll
        for (int d = 0; d < 16; ++d) {
            ak = fmaf(xv[d], swk[d], ak);
            av = fmaf(xv[d], swv[d], av);
        }
        skv[j] = make_float2(ak, av);
    }

    // This thread's query (pre-scaled by log2 e).
    int i = (tile << 7) + t;
    float qi;
    {
        const float4* xr = reinterpret_cast<const float4*>(xb + i * 16);
        float4 x0 = xr[0], x1 = xr[1], x2 = xr[2], x3 = xr[3];
        float xv[16] = { x0.x, x0.y, x0.z, x0.w, x1.x, x1.y, x1.z, x1.w,
                         x2.x, x2.y, x2.z, x2.w, x3.x, x3.y, x3.z, x3.w };
        float aq = sbias[0];
        #pragma unroll
        for (int d = 0; d < 16; ++d) aq = fmaf(xv[d], swq[d], aq);
        qi = aq;
    }
    __syncthreads();

    // Causal softmax-weighted sum over j in [0, i]. (R0-proven mainloop.)
    float den0 = 0.f, den1 = 0.f, num0 = 0.f, num1 = 0.f;
    int j = 0;
    #pragma unroll 4
    for (; j < i; j += 2) {               // j, j+1 both <= i
        float2 a = skv[j];
        float2 c = skv[j + 1];
        float e0 = ex2f(qi * a.x);
        float e1 = ex2f(qi * c.x);
        den0 += e0;  num0 = fmaf(e0, a.y, num0);
        den1 += e1;  num1 = fmaf(e1, c.y, num1);
    }
    if (j == i) {                         // diagonal when i even
        float2 a = skv[j];
        float e = ex2f(qi * a.x);
        den0 += e;  num0 = fmaf(e, a.y, num0);
    }
    float o = (num0 + num1) / (den0 + den1);

    // Rank-1 projection scatter: out[b,i,c] += o * wo[h,c] + bo[c]/16.
    float* orow = out + (b * SS + i) * 16;
    #pragma unroll
    for (int c = 0; c < 16; ++c)
        atomicAdd(orow + c, fmaf(o, swo[c], sbo[c]));
}

// ---------------------------------------------------------------------------
extern "C" void kernel_launch(void* const* d_in, const int* in_sizes, int n_in,
                              void* d_out, int out_size)
{
    const float* x     = (const float*)d_in[0];
    const float* w_qkv = (const float*)d_in[1];
    const float* b_qkv = (const float*)d_in[2];
    const float* w_out = (const float*)d_in[3];
    const float* b_out = (const float*)d_in[4];
    float* out = (float*)d_out;

    cudaMemsetAsync(out, 0, (size_t)out_size * sizeof(float));
    attn_kernel<<<NB, 128>>>(x, w_qkv, b_qkv, w_out, b_out, out);
}

// round 11
// speedup vs baseline: 1.2930x; 1.2930x over previous
#include <cuda_runtime.h>

#define BB 4
#define SS 2048
#define DD 16
#define HH 16
#define NPAIR (BB*HH)      // 64
#define TQ 128
#define NT (SS/TQ)         // 16
#define L2E 1.44269504088896340736f

// Scratch (device globals; no allocation allowed).
__device__ float  g_q [NPAIR*SS];      // q * log2(e), [pair][s]
__device__ float2 g_kv[NPAIR*SS];      // (k, v) interleaved, [pair][s]
__device__ float  g_o [BB*SS*DD];      // attention output, [b][s][h]

__device__ __forceinline__ float ex2f(float x) {
    float r; asm("ex2.approx.ftz.f32 %0, %1;" : "=f"(r) : "f"(x)); return r;
}

// ---------------------------------------------------------------------------
// Kernel 1: qkv projection, write-coalesced.
// Grid 128 x 256 threads. Block covers 64 rows; thread = (s = tid&63,
// head group cg = tid>>6 -> heads cg*4..cg*4+3). Warp lanes span 32
// consecutive s for fixed head set -> all stores coalesced.
// ---------------------------------------------------------------------------
__global__ void __launch_bounds__(256) qkv_kernel(
    const float* __restrict__ x,   // [8192, 16]
    const float* __restrict__ w,   // [16, 48]
    const float* __restrict__ bq)  // [48]
{
    __shared__ float sx[64 * 17];          // padded: (17s+d) % 32 all-distinct
    int tid = threadIdx.x;
    {   // load x tile: 64 rows x 16 floats, float4-coalesced
        int rr = tid >> 2, qq = tid & 3;   // row 0..63, quarter 0..3
        const float4* src = reinterpret_cast<const float4*>(x + (blockIdx.x * 64 + rr) * DD);
        float4 vv = src[qq];
        float* dst = sx + rr * 17 + qq * 4;
        dst[0] = vv.x; dst[1] = vv.y; dst[2] = vv.z; dst[3] = vv.w;
    }
    __syncthreads();

    int s  = tid & 63;
    int cg = tid >> 6;                     // 0..3
    int r  = blockIdx.x * 64 + s;          // global row
    int b  = r >> 11, sl = r & (SS - 1);

    float xv[16];
    #pragma unroll
    for (int d = 0; d < 16; ++d) xv[d] = sx[s * 17 + d];

    #pragma unroll
    for (int u = 0; u < 4; ++u) {
        int h = cg * 4 + u;
        float aq = bq[h], ak = bq[h + 16], av = bq[h + 32];
        #pragma unroll
        for (int d = 0; d < 16; ++d) {
            float xd = xv[d];
            aq = fmaf(xd, w[d * 48 + h],      aq);   // uniform -> broadcast
            ak = fmaf(xd, w[d * 48 + h + 16], ak);
            av = fmaf(xd, w[d * 48 + h + 32], av);
        }
        int idx = (b * HH + h) * SS + sl;
        g_q[idx]  = aq * L2E;              // scale=1, fold log2(e)
        g_kv[idx] = make_float2(ak, av);   // STG.64, warp-coalesced
    }
}

// ---------------------------------------------------------------------------
// Kernel 2: causal scalar-head attention (R0-proven, at MUFU roofline).
// Block = one (pair, query-tile); 128 threads, one query each; heavy-first.
// ---------------------------------------------------------------------------
__global__ void __launch_bounds__(128) attn_kernel()
{
    __shared__ float2 skv[SS];   // 16 KB

    int bx   = blockIdx.x;
    int pair = bx & (NPAIR - 1);
    int tile = NT - 1 - (bx >> 6);         // heavy-first
    int tile_start = tile * TQ;
    int tile_end   = tile_start + TQ;

    // Stage (k,v) prefix [0, tile_end), float4-wide.
    {
        const float4* src = reinterpret_cast<const float4*>(g_kv + pair * SS);
        float4* dst = reinterpret_cast<float4*>(skv);
        int n4 = tile_end >> 1;
        for (int j = threadIdx.x; j < n4; j += TQ) dst[j] = src[j];
    }
    __syncthreads();

    int   i  = tile_start + threadIdx.x;
    float qi = g_q[pair * SS + i];

    float den0 = 0.f, den1 = 0.f, num0 = 0.f, num1 = 0.f;
    int j = 0;
    #pragma unroll 4
    for (; j < i; j += 2) {                // j, j+1 both <= i
        float2 a = skv[j];
        float2 c = skv[j + 1];
        float e0 = ex2f(qi * a.x);
        float e1 = ex2f(qi * c.x);
        den0 += e0;  num0 = fmaf(e0, a.y, num0);
        den1 += e1;  num1 = fmaf(e1, c.y, num1);
    }
    if (j == i) {                          // diagonal when i even
        float2 a = skv[j];
        float e = ex2f(qi * a.x);
        den0 += e;  num0 = fmaf(e, a.y, num0);
    }

    int b = pair >> 4, h = pair & 15;
    g_o[(b * SS + i) * DD + h] = (num0 + num1) / (den0 + den1);
}

// ---------------------------------------------------------------------------
// Kernel 3: output projection (measured 4.6us, launch-floor-bound).
// ---------------------------------------------------------------------------
__global__ void __launch_bounds__(256) proj_kernel(
    const float* __restrict__ wo,  // [16, 16]
    const float* __restrict__ bo,  // [16]
    float* __restrict__ out)       // [8192, 16]
{
    __shared__ float so[256];
    __shared__ float sw[256];
    __shared__ float sb[16];
    int t = threadIdx.x;

    so[t] = g_o[blockIdx.x * 256 + t];     // coalesced
    sw[t] = wo[t];
    if (t < 16) sb[t] = bo[t];
    __syncthreads();

    int rl = t >> 4, c = t & 15;
    float acc = sb[c];
    #pragma unroll
    for (int d = 0; d < 16; ++d)
        acc = fmaf(so[rl * 16 + d], sw[d * 16 + c], acc);

    out[blockIdx.x * 256 + t] = acc;       // coalesced
}

// ---------------------------------------------------------------------------
extern "C" void kernel_launch(void* const* d_in, const int* in_sizes, int n_in,
                              void* d_out, int out_size)
{
    const float* x     = (const float*)d_in[0];
    const float* w_qkv = (const float*)d_in[1];
    const float* b_qkv = (const float*)d_in[2];
    const float* w_out = (const float*)d_in[3];
    const float* b_out = (const float*)d_in[4];
    float* out = (float*)d_out;

    qkv_kernel<<<(BB * SS) / 64, 256>>>(x, w_qkv, b_qkv);
    attn_kernel<<<NPAIR * NT, TQ>>>();
    proj_kernel<<<(BB * SS * DD) / 256, 256>>>(w_out, b_out, out);
}